// round 8
// baseline (speedup 1.0000x reference)
#include <cuda_runtime.h>
#include <cuda_fp16.h>
#include <cstdint>

#define NN 100000
#define D  512

// Scratch (allocation-free rule: __device__ globals)
__device__ __align__(128) __half g_h[(size_t)NN * D];     // fp16 intermediate h
__device__ __align__(128) __half g_ahi[(size_t)NN * D];   // A operand for GEMM
__device__ __align__(128) __half g_w1hi[D * D], g_w1lo[D * D];
__device__ __align__(128) __half g_w2hi[D * D], g_w2lo[D * D];
__device__ float g_rsd[NN];

static __device__ __forceinline__ uint32_t smem_u32(const void* p) {
    uint32_t a;
    asm("{ .reg .u64 t; cvta.to.shared.u64 t, %1; cvt.u32.u64 %0, t; }" : "=r"(a) : "l"(p));
    return a;
}

#define LDSM4(r, addr) \
    asm volatile("ldmatrix.sync.aligned.m8n8.x4.shared.b16 {%0,%1,%2,%3}, [%4];" \
        : "=r"((r)[0]), "=r"((r)[1]), "=r"((r)[2]), "=r"((r)[3]) : "r"(addr))

#define MMA16816(d, a, b0, b1) \
    asm volatile("mma.sync.aligned.m16n8k16.row.col.f32.f16.f16.f32 " \
        "{%0,%1,%2,%3}, {%4,%5,%6,%7}, {%8,%9}, {%0,%1,%2,%3};" \
        : "+f"((d)[0]), "+f"((d)[1]), "+f"((d)[2]), "+f"((d)[3]) \
        : "r"((a)[0]), "r"((a)[1]), "r"((a)[2]), "r"((a)[3]), "r"(b0), "r"(b1))

#define CP16(dst, src, n) \
    asm volatile("cp.async.cg.shared.global [%0], [%1], 16, %2;" \
        :: "r"(dst), "l"(src), "r"(n))
#define CP_COMMIT() asm volatile("cp.async.commit_group;" ::: "memory")
#define CP_WAIT1()  asm volatile("cp.async.wait_group 1;" ::: "memory")

static __device__ __forceinline__ void split2h(float x, float y, uint32_t& h, uint32_t& l) {
    __half2 hb = __floats2half2_rn(x, y);
    float hx = __low2float(hb), hy = __high2float(hb);
    __half2 lb = __floats2half2_rn(x - hx, y - hy);
    h = *reinterpret_cast<uint32_t*>(&hb);
    l = *reinterpret_cast<uint32_t*>(&lb);
}

__global__ void deg_kernel(const int* __restrict__ ei) {
    int i = blockIdx.x * blockDim.x + threadIdx.x;
    if (i >= NN) return;
    int c = 1;
#pragma unroll
    for (int j = 0; j < 3; j++) c += (ei[i * 3 + j] >= 0);
    g_rsd[i] = rsqrtf((float)c);
}

__global__ void tohalf_kernel(const float* __restrict__ src,
                              __half* __restrict__ hi, int n4) {
    int i = blockIdx.x * blockDim.x + threadIdx.x;
    if (i >= n4) return;
    float4 v = ((const float4*)src)[i];
    __half2 a = __floats2half2_rn(v.x, v.y);
    __half2 b = __floats2half2_rn(v.z, v.w);
    ((uint2*)hi)[i] = make_uint2(*(uint32_t*)&a, *(uint32_t*)&b);
}

__global__ void split_kernel(const float* __restrict__ src,
                             __half* __restrict__ hi,
                             __half* __restrict__ lo, int n4) {
    int i = blockIdx.x * blockDim.x + threadIdx.x;
    if (i >= n4) return;
    float4 v = ((const float4*)src)[i];
    uint32_t h0, l0, h1, l1;
    split2h(v.x, v.y, h0, l0);
    split2h(v.z, v.w, h1, l1);
    ((uint2*)hi)[i] = make_uint2(h0, h1);
    ((uint2*)lo)[i] = make_uint2(l0, l1);
}

// ---------------- fp16 2-term HMMA GEMM, 128x256 block, 64x64 warp tiles ------
// Stage (80KB): A[128 rows x 128B] @0, Whi[256 x 128B] @16K, Wlo @48K.
// Row r holds k-chunk of 64 halves as 8 x 16B slots; slot s at phys s^(r&7).
static constexpr int BN = 256;
static constexpr int STAGE_BYTES = 81920;
static constexpr int SMEM_TOTAL  = 2048 + 2 * STAGE_BYTES;

__global__ void __launch_bounds__(256, 1)
gemm_hmma(const __half* __restrict__ Ahi,
          const __half* __restrict__ Whi, const __half* __restrict__ Wlo,
          const float* __restrict__ bias, __half* __restrict__ Ch) {
    extern __shared__ char smem[];
    const int tid = threadIdx.x, lid = tid & 31, wid = tid >> 5;
    const int m0 = blockIdx.y * 128, n0 = blockIdx.x * BN;

    float* biasS = (float*)smem;
    if (tid < BN) biasS[tid] = bias[n0 + tid];
    const uint32_t sb = smem_u32(smem) + 2048;

    // A loader: 2 threads/row; B loader: 1 thread/row (hi+lo)
    const int r  = tid >> 1, h = tid & 1;
    const int rb = tid;
    const bool aval = (m0 + r) < NN;
    const int pa = aval ? 16 : 0;
    const __half* aSrc = Ahi + (size_t)(m0 + (aval ? r : 0)) * D;
    const __half* bHs  = Whi + (size_t)(n0 + rb) * D;
    const __half* bLs  = Wlo + (size_t)(n0 + rb) * D;
    const uint32_t aRow = sb + r * 128;
    const uint32_t bRow = sb + 16384 + rb * 128;   // hi; lo at +32768

    float acc[4][8][4];
#pragma unroll
    for (int mt = 0; mt < 4; mt++)
#pragma unroll
        for (int nt = 0; nt < 8; nt++)
#pragma unroll
            for (int j = 0; j < 4; j++) acc[mt][nt][j] = 0.f;

    auto issue = [&](int c) {
        const int st = c & 1;
        const int ko = c * 64;
        const uint32_t dA = aRow + st * STAGE_BYTES;
#pragma unroll
        for (int j = 0; j < 4; j++) {
            const int s = 4 * h + j;
            CP16(dA + ((s ^ (r & 7)) << 4), aSrc + ko + s * 8, pa);
        }
        const uint32_t dB = bRow + st * STAGE_BYTES;
#pragma unroll
        for (int s = 0; s < 8; s++) {
            const uint32_t so = (uint32_t)((s ^ (rb & 7)) << 4);
            CP16(dB + so,         bHs + ko + s * 8, 16);
            CP16(dB + 32768 + so, bLs + ko + s * 8, 16);
        }
    };

    const int mbase = (wid & 1) * 64, nbase = (wid >> 1) * 64;
    const int q = lid >> 3, rr = lid & 7;

    auto compute = [&](int st) {
        const uint32_t aT = sb + st * STAGE_BYTES;
        const uint32_t bT = aT + 16384;
#pragma unroll
        for (int ks = 0; ks < 4; ks++) {
            uint32_t ah[4][4];
#pragma unroll
            for (int mt = 0; mt < 4; mt++) {
                int row = mbase + mt * 16 + (q & 1) * 8 + rr;
                int ch  = 2 * ks + (q >> 1);
                LDSM4(ah[mt], aT + row * 128 + ((ch ^ (row & 7)) << 4));
            }
#pragma unroll
            for (int p = 0; p < 4; p++) {
                uint32_t bh[4], bl[4];
                int nrow = nbase + p * 16 + (q >> 1) * 8 + rr;
                int ch   = 2 * ks + (q & 1);
                uint32_t off = (uint32_t)(nrow * 128 + ((ch ^ (nrow & 7)) << 4));
                LDSM4(bh, bT + off);
                LDSM4(bl, bT + 32768 + off);
#pragma unroll
                for (int mt = 0; mt < 4; mt++)
#pragma unroll
                    for (int j = 0; j < 2; j++) {
                        float* d = acc[mt][2 * p + j];
                        MMA16816(d, ah[mt], bh[2 * j], bh[2 * j + 1]);
                        MMA16816(d, ah[mt], bl[2 * j], bl[2 * j + 1]);
                    }
            }
        }
    };

    issue(0); CP_COMMIT();
    issue(1); CP_COMMIT();

#pragma unroll 1
    for (int c = 0; c < 8; c++) {
        CP_WAIT1();
        __syncthreads();
        compute(c & 1);
        __syncthreads();
        if (c + 2 < 8) issue(c + 2);
        CP_COMMIT();
    }

    // epilogue: half((acc + bias) * rsd)
#pragma unroll
    for (int mt = 0; mt < 4; mt++)
#pragma unroll
        for (int half = 0; half < 2; half++) {
            int row = m0 + mbase + mt * 16 + (lid >> 2) + half * 8;
            if (row < NN) {
                float rs = g_rsd[row];
#pragma unroll
                for (int nt = 0; nt < 8; nt++) {
                    int colrel = nbase + nt * 8 + (lid & 3) * 2;
                    __half2 hv = __floats2half2_rn(
                        (acc[mt][nt][half * 2 + 0] + biasS[colrel + 0]) * rs,
                        (acc[mt][nt][half * 2 + 1] + biasS[colrel + 1]) * rs);
                    *(uint32_t*)(Ch + (size_t)row * D + n0 + colrel) = *(uint32_t*)&hv;
                }
            }
        }
}

static __device__ __forceinline__ void addh4(float& a0, float& a1, float& a2, float& a3, uint2 v) {
    __half2 p = *reinterpret_cast<__half2*>(&v.x);
    __half2 q = *reinterpret_cast<__half2*>(&v.y);
    a0 += __low2float(p); a1 += __high2float(p);
    a2 += __low2float(q); a3 += __high2float(q);
}

__global__ void agg_half_kernel(const __half* __restrict__ h,
                                const int* __restrict__ ei,
                                __half* __restrict__ hi) {
    const size_t node = blockIdx.x;
    const int t = threadIdx.x;
    const uint2* hv = (const uint2*)h;

    float a0 = 0.f, a1 = 0.f, a2 = 0.f, a3 = 0.f;
    addh4(a0, a1, a2, a3, hv[node * 128 + t]);
    int e0 = ei[node * 3 + 0];
    int e1 = ei[node * 3 + 1];
    int e2 = ei[node * 3 + 2];
    if (e0 >= 0) addh4(a0, a1, a2, a3, hv[(size_t)e0 * 128 + t]);
    if (e1 >= 0) addh4(a0, a1, a2, a3, hv[(size_t)e1 * 128 + t]);
    if (e2 >= 0) addh4(a0, a1, a2, a3, hv[(size_t)e2 * 128 + t]);

    const float rs = g_rsd[node];
    a0 *= rs; a1 *= rs; a2 *= rs; a3 *= rs;
    a0 = a0 > 0.f ? a0 : expm1f(a0);
    a1 = a1 > 0.f ? a1 : expm1f(a1);
    a2 = a2 > 0.f ? a2 : expm1f(a2);
    a3 = a3 > 0.f ? a3 : expm1f(a3);

    __half2 p = __floats2half2_rn(a0, a1);
    __half2 q = __floats2half2_rn(a2, a3);
    ((uint2*)hi)[node * 128 + t] = make_uint2(*(uint32_t*)&p, *(uint32_t*)&q);
}

__global__ void agg_final_kernel(const __half* __restrict__ h,
                                 const int* __restrict__ ei,
                                 float* __restrict__ out) {
    const size_t node = blockIdx.x;
    const int t = threadIdx.x;
    const uint2* hv = (const uint2*)h;

    float a0 = 0.f, a1 = 0.f, a2 = 0.f, a3 = 0.f;
    addh4(a0, a1, a2, a3, hv[node * 128 + t]);
    int e0 = ei[node * 3 + 0];
    int e1 = ei[node * 3 + 1];
    int e2 = ei[node * 3 + 2];
    if (e0 >= 0) addh4(a0, a1, a2, a3, hv[(size_t)e0 * 128 + t]);
    if (e1 >= 0) addh4(a0, a1, a2, a3, hv[(size_t)e1 * 128 + t]);
    if (e2 >= 0) addh4(a0, a1, a2, a3, hv[(size_t)e2 * 128 + t]);

    const float rs = g_rsd[node];
    a0 *= rs; a1 *= rs; a2 *= rs; a3 *= rs;
    float4 o;
    o.x = a0 > 0.f ? a0 : expm1f(a0);
    o.y = a1 > 0.f ? a1 : expm1f(a1);
    o.z = a2 > 0.f ? a2 : expm1f(a2);
    o.w = a3 > 0.f ? a3 : expm1f(a3);
    ((float4*)out)[node * 128 + t] = o;
}

extern "C" void kernel_launch(void* const* d_in, const int* in_sizes, int n_in,
                              void* d_out, int out_size) {
    const float* x  = nullptr;
    const int*   ei = nullptr;
    const float* Wt[2] = {nullptr, nullptr};
    const float* bt[2] = {nullptr, nullptr};
    int wi = 0, bi = 0;
    for (int i = 0; i < n_in; i++) {
        int sz = in_sizes[i];
        if (sz == NN * D)      x = (const float*)d_in[i];
        else if (sz == NN * 3) ei = (const int*)d_in[i];
        else if (sz == D * D)  { if (wi < 2) Wt[wi++] = (const float*)d_in[i]; }
        else if (sz == D)      { if (bi < 2) bt[bi++] = (const float*)d_in[i]; }
    }
    float* out = (float*)d_out;

    void *ph, *pah, *pw1h, *pw1l, *pw2h, *pw2l;
    cudaGetSymbolAddress(&ph,  g_h);
    cudaGetSymbolAddress(&pah, g_ahi);
    cudaGetSymbolAddress(&pw1h, g_w1hi);
    cudaGetSymbolAddress(&pw1l, g_w1lo);
    cudaGetSymbolAddress(&pw2h, g_w2hi);
    cudaGetSymbolAddress(&pw2l, g_w2lo);
    __half* hbuf = (__half*)ph;
    __half* ahi = (__half*)pah;
    __half *w1hi = (__half*)pw1h, *w1lo = (__half*)pw1l;
    __half *w2hi = (__half*)pw2h, *w2lo = (__half*)pw2l;

    cudaFuncSetAttribute(gemm_hmma, cudaFuncAttributeMaxDynamicSharedMemorySize, SMEM_TOTAL);

    deg_kernel<<<(NN + 255) / 256, 256>>>(ei);
    tohalf_kernel<<<(NN * D / 4 + 255) / 256, 256>>>(x, ahi, NN * D / 4);
    split_kernel<<<(D * D / 4 + 255) / 256, 256>>>(Wt[0], w1hi, w1lo, D * D / 4);
    split_kernel<<<(D * D / 4 + 255) / 256, 256>>>(Wt[1], w2hi, w2lo, D * D / 4);

    dim3 ggrid(D / BN, (NN + 127) / 128);  // (2, 782)
    gemm_hmma<<<ggrid, 256, SMEM_TOTAL>>>(ahi, w1hi, w1lo, bt[0], hbuf);
    agg_half_kernel<<<NN, 128>>>(hbuf, ei, ahi);
    gemm_hmma<<<ggrid, 256, SMEM_TOTAL>>>(ahi, w2hi, w2lo, bt[1], hbuf);
    agg_final_kernel<<<NN, 128>>>(hbuf, ei, out);
}

// round 10
// speedup vs baseline: 1.3621x; 1.3621x over previous
#include <cuda_runtime.h>
#include <cuda_fp16.h>
#include <cstdint>

#define NN 100000
#define D  512

// Scratch (allocation-free rule: __device__ globals)
__device__ __align__(128) __half g_h[(size_t)NN * D];     // fp16 intermediate h
__device__ __align__(128) __half g_ahi[(size_t)NN * D];   // A operand for GEMM
__device__ __align__(128) __half g_w1hi[D * D], g_w1lo[D * D];
__device__ __align__(128) __half g_w2hi[D * D], g_w2lo[D * D];
__device__ float g_rsd[NN];

static __device__ __forceinline__ uint32_t smem_u32(const void* p) {
    uint32_t a;
    asm("{ .reg .u64 t; cvta.to.shared.u64 t, %1; cvt.u32.u64 %0, t; }" : "=r"(a) : "l"(p));
    return a;
}

#define LDSM4(r, addr) \
    asm volatile("ldmatrix.sync.aligned.m8n8.x4.shared.b16 {%0,%1,%2,%3}, [%4];" \
        : "=r"((r)[0]), "=r"((r)[1]), "=r"((r)[2]), "=r"((r)[3]) : "r"(addr))

#define MMA16816(d, a, b0, b1) \
    asm volatile("mma.sync.aligned.m16n8k16.row.col.f32.f16.f16.f32 " \
        "{%0,%1,%2,%3}, {%4,%5,%6,%7}, {%8,%9}, {%0,%1,%2,%3};" \
        : "+f"((d)[0]), "+f"((d)[1]), "+f"((d)[2]), "+f"((d)[3]) \
        : "r"((a)[0]), "r"((a)[1]), "r"((a)[2]), "r"((a)[3]), "r"(b0), "r"(b1))

#define CP16(dst, src, n) \
    asm volatile("cp.async.cg.shared.global [%0], [%1], 16, %2;" \
        :: "r"(dst), "l"(src), "r"(n))
#define CP_COMMIT() asm volatile("cp.async.commit_group;" ::: "memory")
#define CP_WAIT1()  asm volatile("cp.async.wait_group 1;" ::: "memory")

static __device__ __forceinline__ void split2h(float x, float y, uint32_t& h, uint32_t& l) {
    __half2 hb = __floats2half2_rn(x, y);
    float hx = __low2float(hb), hy = __high2float(hb);
    __half2 lb = __floats2half2_rn(x - hx, y - hy);
    h = *reinterpret_cast<uint32_t*>(&hb);
    l = *reinterpret_cast<uint32_t*>(&lb);
}

__global__ void deg_kernel(const int* __restrict__ ei) {
    int i = blockIdx.x * blockDim.x + threadIdx.x;
    if (i >= NN) return;
    int c = 1;
#pragma unroll
    for (int j = 0; j < 3; j++) c += (ei[i * 3 + j] >= 0);
    g_rsd[i] = rsqrtf((float)c);
}

__global__ void tohalf_kernel(const float* __restrict__ src,
                              __half* __restrict__ hi, int n4) {
    int i = blockIdx.x * blockDim.x + threadIdx.x;
    if (i >= n4) return;
    float4 v = ((const float4*)src)[i];
    __half2 a = __floats2half2_rn(v.x, v.y);
    __half2 b = __floats2half2_rn(v.z, v.w);
    ((uint2*)hi)[i] = make_uint2(*(uint32_t*)&a, *(uint32_t*)&b);
}

__global__ void split_kernel(const float* __restrict__ src,
                             __half* __restrict__ hi,
                             __half* __restrict__ lo, int n4) {
    int i = blockIdx.x * blockDim.x + threadIdx.x;
    if (i >= n4) return;
    float4 v = ((const float4*)src)[i];
    uint32_t h0, l0, h1, l1;
    split2h(v.x, v.y, h0, l0);
    split2h(v.z, v.w, h1, l1);
    ((uint2*)hi)[i] = make_uint2(h0, h1);
    ((uint2*)lo)[i] = make_uint2(l0, l1);
}

// ---------------- fp16 2-term HMMA GEMM, 128x128 block, 64x32 warp tiles ------
// Stage (48KB): Ahi[128 x 128B] @0, Whi @16K, Wlo @32K. Row r = 8 x 16B slots,
// slot s (k [8s..8s+8)) at phys slot s^(r&7). 2-stage cp.async, 2 CTAs/SM.
static constexpr int STAGE_BYTES = 49152;
static constexpr int SMEM_TOTAL  = 1024 + 2 * STAGE_BYTES;

__global__ void __launch_bounds__(256, 2)
gemm_hmma(const __half* __restrict__ Ahi,
          const __half* __restrict__ Whi, const __half* __restrict__ Wlo,
          const float* __restrict__ bias, __half* __restrict__ Ch) {
    extern __shared__ char smem[];
    const int tid = threadIdx.x, lid = tid & 31, wid = tid >> 5;
    const int m0 = blockIdx.y * 128, n0 = blockIdx.x * 128;

    float* biasS = (float*)smem;
    if (tid < 128) biasS[tid] = bias[n0 + tid];
    const uint32_t sb = smem_u32(smem) + 1024;

    const int r = tid >> 1, h = tid & 1;
    const bool aval = (m0 + r) < NN;
    const int pa = aval ? 16 : 0;
    const __half* aSrc = Ahi + (size_t)(m0 + (aval ? r : 0)) * D;
    const __half* bHs  = Whi + (size_t)(n0 + r) * D;
    const __half* bLs  = Wlo + (size_t)(n0 + r) * D;

    float acc[4][4][4];
#pragma unroll
    for (int mt = 0; mt < 4; mt++)
#pragma unroll
        for (int nt = 0; nt < 4; nt++)
#pragma unroll
            for (int j = 0; j < 4; j++) acc[mt][nt][j] = 0.f;

    auto issue = [&](int c) {
        const int st = c & 1;
        const uint32_t dA = sb + st * STAGE_BYTES + r * 128;
        const int ko = c * 64;
#pragma unroll
        for (int j = 0; j < 4; j++) {
            const int s = 4 * h + j;
            const uint32_t so = (uint32_t)((s ^ (r & 7)) << 4);
            CP16(dA + so,         aSrc + ko + s * 8, pa);
            CP16(dA + 16384 + so, bHs  + ko + s * 8, 16);
            CP16(dA + 32768 + so, bLs  + ko + s * 8, 16);
        }
    };

    // warp grid: 2 along M (64 rows each), 4 along N (32 cols each)
    const int mbase = (wid & 1) * 64, nbase = (wid >> 1) * 32;
    const int q = lid >> 3, rr = lid & 7;

    auto compute = [&](int st) {
        const uint32_t aT = sb + st * STAGE_BYTES;
        const uint32_t bT = aT + 16384;   // Whi; Wlo at bT + 16384
#pragma unroll
        for (int ks = 0; ks < 4; ks++) {
            uint32_t ah[4][4];
#pragma unroll
            for (int mt = 0; mt < 4; mt++) {
                int row = mbase + mt * 16 + (q & 1) * 8 + rr;
                int ch  = 2 * ks + (q >> 1);
                LDSM4(ah[mt], aT + row * 128 + ((ch ^ (row & 7)) << 4));
            }
#pragma unroll
            for (int p = 0; p < 2; p++) {
                uint32_t bh[4], bl[4];
                int nrow = nbase + p * 16 + (q >> 1) * 8 + rr;
                int ch   = 2 * ks + (q & 1);
                uint32_t off = (uint32_t)(nrow * 128 + ((ch ^ (nrow & 7)) << 4));
                LDSM4(bh, bT + off);
                LDSM4(bl, bT + 16384 + off);   // FIX: Wlo is 16K past Whi
#pragma unroll
                for (int mt = 0; mt < 4; mt++)
#pragma unroll
                    for (int j = 0; j < 2; j++) {
                        float* d = acc[mt][2 * p + j];
                        MMA16816(d, ah[mt], bh[2 * j], bh[2 * j + 1]);
                        MMA16816(d, ah[mt], bl[2 * j], bl[2 * j + 1]);
                    }
            }
        }
    };

    issue(0); CP_COMMIT();
    issue(1); CP_COMMIT();

#pragma unroll 1
    for (int c = 0; c < 8; c++) {
        CP_WAIT1();
        __syncthreads();
        compute(c & 1);
        __syncthreads();
        if (c + 2 < 8) issue(c + 2);
        CP_COMMIT();
    }

    // epilogue: half((acc + bias) * rsd)
#pragma unroll
    for (int mt = 0; mt < 4; mt++)
#pragma unroll
        for (int half = 0; half < 2; half++) {
            int row = m0 + mbase + mt * 16 + (lid >> 2) + half * 8;
            if (row < NN) {
                float rs = g_rsd[row];
#pragma unroll
                for (int nt = 0; nt < 4; nt++) {
                    int colrel = nbase + nt * 8 + (lid & 3) * 2;
                    __half2 hv = __floats2half2_rn(
                        (acc[mt][nt][half * 2 + 0] + biasS[colrel + 0]) * rs,
                        (acc[mt][nt][half * 2 + 1] + biasS[colrel + 1]) * rs);
                    *(uint32_t*)(Ch + (size_t)row * D + n0 + colrel) = *(uint32_t*)&hv;
                }
            }
        }
}

static __device__ __forceinline__ void addh4(float& a0, float& a1, float& a2, float& a3, uint2 v) {
    __half2 p = *reinterpret_cast<__half2*>(&v.x);
    __half2 q = *reinterpret_cast<__half2*>(&v.y);
    a0 += __low2float(p); a1 += __high2float(p);
    a2 += __low2float(q); a3 += __high2float(q);
}

__global__ void agg_half_kernel(const __half* __restrict__ h,
                                const int* __restrict__ ei,
                                __half* __restrict__ hi) {
    const size_t node = blockIdx.x;
    const int t = threadIdx.x;
    const uint2* hv = (const uint2*)h;

    float a0 = 0.f, a1 = 0.f, a2 = 0.f, a3 = 0.f;
    addh4(a0, a1, a2, a3, hv[node * 128 + t]);
    int e0 = ei[node * 3 + 0];
    int e1 = ei[node * 3 + 1];
    int e2 = ei[node * 3 + 2];
    if (e0 >= 0) addh4(a0, a1, a2, a3, hv[(size_t)e0 * 128 + t]);
    if (e1 >= 0) addh4(a0, a1, a2, a3, hv[(size_t)e1 * 128 + t]);
    if (e2 >= 0) addh4(a0, a1, a2, a3, hv[(size_t)e2 * 128 + t]);

    const float rs = g_rsd[node];
    a0 *= rs; a1 *= rs; a2 *= rs; a3 *= rs;
    a0 = a0 > 0.f ? a0 : expm1f(a0);
    a1 = a1 > 0.f ? a1 : expm1f(a1);
    a2 = a2 > 0.f ? a2 : expm1f(a2);
    a3 = a3 > 0.f ? a3 : expm1f(a3);

    __half2 p = __floats2half2_rn(a0, a1);
    __half2 q = __floats2half2_rn(a2, a3);
    ((uint2*)hi)[node * 128 + t] = make_uint2(*(uint32_t*)&p, *(uint32_t*)&q);
}

__global__ void agg_final_kernel(const __half* __restrict__ h,
                                 const int* __restrict__ ei,
                                 float* __restrict__ out) {
    const size_t node = blockIdx.x;
    const int t = threadIdx.x;
    const uint2* hv = (const uint2*)h;

    float a0 = 0.f, a1 = 0.f, a2 = 0.f, a3 = 0.f;
    addh4(a0, a1, a2, a3, hv[node * 128 + t]);
    int e0 = ei[node * 3 + 0];
    int e1 = ei[node * 3 + 1];
    int e2 = ei[node * 3 + 2];
    if (e0 >= 0) addh4(a0, a1, a2, a3, hv[(size_t)e0 * 128 + t]);
    if (e1 >= 0) addh4(a0, a1, a2, a3, hv[(size_t)e1 * 128 + t]);
    if (e2 >= 0) addh4(a0, a1, a2, a3, hv[(size_t)e2 * 128 + t]);

    const float rs = g_rsd[node];
    a0 *= rs; a1 *= rs; a2 *= rs; a3 *= rs;
    float4 o;
    o.x = a0 > 0.f ? a0 : expm1f(a0);
    o.y = a1 > 0.f ? a1 : expm1f(a1);
    o.z = a2 > 0.f ? a2 : expm1f(a2);
    o.w = a3 > 0.f ? a3 : expm1f(a3);
    ((float4*)out)[node * 128 + t] = o;
}

extern "C" void kernel_launch(void* const* d_in, const int* in_sizes, int n_in,
                              void* d_out, int out_size) {
    const float* x  = nullptr;
    const int*   ei = nullptr;
    const float* Wt[2] = {nullptr, nullptr};
    const float* bt[2] = {nullptr, nullptr};
    int wi = 0, bi = 0;
    for (int i = 0; i < n_in; i++) {
        int sz = in_sizes[i];
        if (sz == NN * D)      x = (const float*)d_in[i];
        else if (sz == NN * 3) ei = (const int*)d_in[i];
        else if (sz == D * D)  { if (wi < 2) Wt[wi++] = (const float*)d_in[i]; }
        else if (sz == D)      { if (bi < 2) bt[bi++] = (const float*)d_in[i]; }
    }
    float* out = (float*)d_out;

    void *ph, *pah, *pw1h, *pw1l, *pw2h, *pw2l;
    cudaGetSymbolAddress(&ph,  g_h);
    cudaGetSymbolAddress(&pah, g_ahi);
    cudaGetSymbolAddress(&pw1h, g_w1hi);
    cudaGetSymbolAddress(&pw1l, g_w1lo);
    cudaGetSymbolAddress(&pw2h, g_w2hi);
    cudaGetSymbolAddress(&pw2l, g_w2lo);
    __half* hbuf = (__half*)ph;
    __half* ahi = (__half*)pah;
    __half *w1hi = (__half*)pw1h, *w1lo = (__half*)pw1l;
    __half *w2hi = (__half*)pw2h, *w2lo = (__half*)pw2l;

    cudaFuncSetAttribute(gemm_hmma, cudaFuncAttributeMaxDynamicSharedMemorySize, SMEM_TOTAL);

    deg_kernel<<<(NN + 255) / 256, 256>>>(ei);
    tohalf_kernel<<<(NN * D / 4 + 255) / 256, 256>>>(x, ahi, NN * D / 4);
    split_kernel<<<(D * D / 4 + 255) / 256, 256>>>(Wt[0], w1hi, w1lo, D * D / 4);
    split_kernel<<<(D * D / 4 + 255) / 256, 256>>>(Wt[1], w2hi, w2lo, D * D / 4);

    dim3 ggrid(D / 128, (NN + 127) / 128);  // (4, 782)
    gemm_hmma<<<ggrid, 256, SMEM_TOTAL>>>(ahi, w1hi, w1lo, bt[0], hbuf);
    agg_half_kernel<<<NN, 128>>>(hbuf, ei, ahi);
    gemm_hmma<<<ggrid, 256, SMEM_TOTAL>>>(ahi, w2hi, w2lo, bt[1], hbuf);
    agg_final_kernel<<<NN, 128>>>(hbuf, ei, out);
}

// round 11
// speedup vs baseline: 1.8031x; 1.3238x over previous
#include <cuda_runtime.h>
#include <cuda_fp16.h>
#include <cstdint>

#define NN 100000
#define D  512

// Scratch (allocation-free rule: __device__ globals)
__device__ __align__(128) __half g_h[(size_t)NN * D];     // fp16 intermediate h
__device__ __align__(128) __half g_ahi[(size_t)NN * D];   // A operand for GEMM
__device__ __align__(128) __half g_w1[D * D], g_w2[D * D];
__device__ float g_rsd[NN];

static __device__ __forceinline__ uint32_t smem_u32(const void* p) {
    uint32_t a;
    asm("{ .reg .u64 t; cvta.to.shared.u64 t, %1; cvt.u32.u64 %0, t; }" : "=r"(a) : "l"(p));
    return a;
}

#define LDSM4(r, addr) \
    asm volatile("ldmatrix.sync.aligned.m8n8.x4.shared.b16 {%0,%1,%2,%3}, [%4];" \
        : "=r"((r)[0]), "=r"((r)[1]), "=r"((r)[2]), "=r"((r)[3]) : "r"(addr))

#define MMA16816(d, a, b0, b1) \
    asm volatile("mma.sync.aligned.m16n8k16.row.col.f32.f16.f16.f32 " \
        "{%0,%1,%2,%3}, {%4,%5,%6,%7}, {%8,%9}, {%0,%1,%2,%3};" \
        : "+f"((d)[0]), "+f"((d)[1]), "+f"((d)[2]), "+f"((d)[3]) \
        : "r"((a)[0]), "r"((a)[1]), "r"((a)[2]), "r"((a)[3]), "r"(b0), "r"(b1))

#define CP16(dst, src, n) \
    asm volatile("cp.async.cg.shared.global [%0], [%1], 16, %2;" \
        :: "r"(dst), "l"(src), "r"(n))
#define CP_COMMIT() asm volatile("cp.async.commit_group;" ::: "memory")
#define CP_WAIT1()  asm volatile("cp.async.wait_group 1;" ::: "memory")

__global__ void deg_kernel(const int* __restrict__ ei) {
    int i = blockIdx.x * blockDim.x + threadIdx.x;
    if (i >= NN) return;
    int c = 1;
#pragma unroll
    for (int j = 0; j < 3; j++) c += (ei[i * 3 + j] >= 0);
    g_rsd[i] = rsqrtf((float)c);
}

// fp32 -> fp16 (round-to-nearest)
__global__ void tohalf_kernel(const float* __restrict__ src,
                              __half* __restrict__ hi, int n4) {
    int i = blockIdx.x * blockDim.x + threadIdx.x;
    if (i >= n4) return;
    float4 v = ((const float4*)src)[i];
    __half2 a = __floats2half2_rn(v.x, v.y);
    __half2 b = __floats2half2_rn(v.z, v.w);
    ((uint2*)hi)[i] = make_uint2(*(uint32_t*)&a, *(uint32_t*)&b);
}

// ---------------- single-term fp16 HMMA GEMM, 128x128 block, 64x32 warp tiles -
// Stage (32KB): A[128 x 128B] @0, W @16K. Row r = 8 x 16B slots,
// slot s (k [8s..8s+8)) at phys slot s^(r&7). 3-stage cp.async, 1 sync/chunk.
static constexpr int STAGE_BYTES = 32768;
static constexpr int NSTAGE = 3;
static constexpr int SMEM_TOTAL  = 1024 + NSTAGE * STAGE_BYTES;

__global__ void __launch_bounds__(256, 2)
gemm_hmma(const __half* __restrict__ Ahi, const __half* __restrict__ W,
          const float* __restrict__ bias, __half* __restrict__ Ch) {
    extern __shared__ char smem[];
    const int tid = threadIdx.x, lid = tid & 31, wid = tid >> 5;
    const int m0 = blockIdx.y * 128, n0 = blockIdx.x * 128;

    float* biasS = (float*)smem;
    if (tid < 128) biasS[tid] = bias[n0 + tid];
    const uint32_t sb = smem_u32(smem) + 1024;

    const int r = tid >> 1, h = tid & 1;
    const bool aval = (m0 + r) < NN;
    const int pa = aval ? 16 : 0;
    const __half* aSrc = Ahi + (size_t)(m0 + (aval ? r : 0)) * D;
    const __half* bSrc = W   + (size_t)(n0 + r) * D;

    float acc[4][4][4];
#pragma unroll
    for (int mt = 0; mt < 4; mt++)
#pragma unroll
        for (int nt = 0; nt < 4; nt++)
#pragma unroll
            for (int j = 0; j < 4; j++) acc[mt][nt][j] = 0.f;

    auto issue = [&](int c) {
        const int st = c % NSTAGE;
        const uint32_t dA = sb + st * STAGE_BYTES + r * 128;
        const int ko = c * 64;
#pragma unroll
        for (int j = 0; j < 4; j++) {
            const int s = 4 * h + j;
            const uint32_t so = (uint32_t)((s ^ (r & 7)) << 4);
            CP16(dA + so,         aSrc + ko + s * 8, pa);
            CP16(dA + 16384 + so, bSrc + ko + s * 8, 16);
        }
    };

    // warp grid: 2 along M (64 rows each), 4 along N (32 cols each)
    const int mbase = (wid & 1) * 64, nbase = (wid >> 1) * 32;
    const int q = lid >> 3, rr = lid & 7;

    auto compute = [&](int st) {
        const uint32_t aT = sb + st * STAGE_BYTES;
        const uint32_t bT = aT + 16384;
#pragma unroll
        for (int ks = 0; ks < 4; ks++) {
            uint32_t ah[4][4];
#pragma unroll
            for (int mt = 0; mt < 4; mt++) {
                int row = mbase + mt * 16 + (q & 1) * 8 + rr;
                int ch  = 2 * ks + (q >> 1);
                LDSM4(ah[mt], aT + row * 128 + ((ch ^ (row & 7)) << 4));
            }
#pragma unroll
            for (int p = 0; p < 2; p++) {
                uint32_t bh[4];
                int nrow = nbase + p * 16 + (q >> 1) * 8 + rr;
                int ch   = 2 * ks + (q & 1);
                LDSM4(bh, bT + (uint32_t)(nrow * 128 + ((ch ^ (nrow & 7)) << 4)));
#pragma unroll
                for (int mt = 0; mt < 4; mt++)
#pragma unroll
                    for (int j = 0; j < 2; j++)
                        MMA16816(acc[mt][2 * p + j], ah[mt], bh[2 * j], bh[2 * j + 1]);
            }
        }
    };

    issue(0); CP_COMMIT();
    issue(1); CP_COMMIT();

#pragma unroll 1
    for (int c = 0; c < 8; c++) {
        CP_WAIT1();            // stage c resident (<=1 group pending)
        __syncthreads();       // all warps done with stage (c-1)%3 reads
        if (c + 2 < 8) issue(c + 2);   // writes stage (c+2)%3 == (c-1)%3
        CP_COMMIT();           // uniform group count (may be empty)
        compute(c % NSTAGE);
    }

    // epilogue: half((acc + bias) * rsd)
#pragma unroll
    for (int mt = 0; mt < 4; mt++)
#pragma unroll
        for (int half = 0; half < 2; half++) {
            int row = m0 + mbase + mt * 16 + (lid >> 2) + half * 8;
            if (row < NN) {
                float rs = g_rsd[row];
#pragma unroll
                for (int nt = 0; nt < 4; nt++) {
                    int colrel = nbase + nt * 8 + (lid & 3) * 2;
                    __half2 hv = __floats2half2_rn(
                        (acc[mt][nt][half * 2 + 0] + biasS[colrel + 0]) * rs,
                        (acc[mt][nt][half * 2 + 1] + biasS[colrel + 1]) * rs);
                    *(uint32_t*)(Ch + (size_t)row * D + n0 + colrel) = *(uint32_t*)&hv;
                }
            }
        }
}

static __device__ __forceinline__ void addh4(float& a0, float& a1, float& a2, float& a3, uint2 v) {
    __half2 p = *reinterpret_cast<__half2*>(&v.x);
    __half2 q = *reinterpret_cast<__half2*>(&v.y);
    a0 += __low2float(p); a1 += __high2float(p);
    a2 += __low2float(q); a3 += __high2float(q);
}

__global__ void agg_half_kernel(const __half* __restrict__ h,
                                const int* __restrict__ ei,
                                __half* __restrict__ hi) {
    const size_t node = blockIdx.x;
    const int t = threadIdx.x;
    const uint2* hv = (const uint2*)h;

    float a0 = 0.f, a1 = 0.f, a2 = 0.f, a3 = 0.f;
    addh4(a0, a1, a2, a3, hv[node * 128 + t]);
    int e0 = ei[node * 3 + 0];
    int e1 = ei[node * 3 + 1];
    int e2 = ei[node * 3 + 2];
    if (e0 >= 0) addh4(a0, a1, a2, a3, hv[(size_t)e0 * 128 + t]);
    if (e1 >= 0) addh4(a0, a1, a2, a3, hv[(size_t)e1 * 128 + t]);
    if (e2 >= 0) addh4(a0, a1, a2, a3, hv[(size_t)e2 * 128 + t]);

    const float rs = g_rsd[node];
    a0 *= rs; a1 *= rs; a2 *= rs; a3 *= rs;
    a0 = a0 > 0.f ? a0 : expm1f(a0);
    a1 = a1 > 0.f ? a1 : expm1f(a1);
    a2 = a2 > 0.f ? a2 : expm1f(a2);
    a3 = a3 > 0.f ? a3 : expm1f(a3);

    __half2 p = __floats2half2_rn(a0, a1);
    __half2 q = __floats2half2_rn(a2, a3);
    ((uint2*)hi)[node * 128 + t] = make_uint2(*(uint32_t*)&p, *(uint32_t*)&q);
}

__global__ void agg_final_kernel(const __half* __restrict__ h,
                                 const int* __restrict__ ei,
                                 float* __restrict__ out) {
    const size_t node = blockIdx.x;
    const int t = threadIdx.x;
    const uint2* hv = (const uint2*)h;

    float a0 = 0.f, a1 = 0.f, a2 = 0.f, a3 = 0.f;
    addh4(a0, a1, a2, a3, hv[node * 128 + t]);
    int e0 = ei[node * 3 + 0];
    int e1 = ei[node * 3 + 1];
    int e2 = ei[node * 3 + 2];
    if (e0 >= 0) addh4(a0, a1, a2, a3, hv[(size_t)e0 * 128 + t]);
    if (e1 >= 0) addh4(a0, a1, a2, a3, hv[(size_t)e1 * 128 + t]);
    if (e2 >= 0) addh4(a0, a1, a2, a3, hv[(size_t)e2 * 128 + t]);

    const float rs = g_rsd[node];
    a0 *= rs; a1 *= rs; a2 *= rs; a3 *= rs;
    float4 o;
    o.x = a0 > 0.f ? a0 : expm1f(a0);
    o.y = a1 > 0.f ? a1 : expm1f(a1);
    o.z = a2 > 0.f ? a2 : expm1f(a2);
    o.w = a3 > 0.f ? a3 : expm1f(a3);
    ((float4*)out)[node * 128 + t] = o;
}

extern "C" void kernel_launch(void* const* d_in, const int* in_sizes, int n_in,
                              void* d_out, int out_size) {
    const float* x  = nullptr;
    const int*   ei = nullptr;
    const float* Wt[2] = {nullptr, nullptr};
    const float* bt[2] = {nullptr, nullptr};
    int wi = 0, bi = 0;
    for (int i = 0; i < n_in; i++) {
        int sz = in_sizes[i];
        if (sz == NN * D)      x = (const float*)d_in[i];
        else if (sz == NN * 3) ei = (const int*)d_in[i];
        else if (sz == D * D)  { if (wi < 2) Wt[wi++] = (const float*)d_in[i]; }
        else if (sz == D)      { if (bi < 2) bt[bi++] = (const float*)d_in[i]; }
    }
    float* out = (float*)d_out;

    void *ph, *pah, *pw1, *pw2;
    cudaGetSymbolAddress(&ph,  g_h);
    cudaGetSymbolAddress(&pah, g_ahi);
    cudaGetSymbolAddress(&pw1, g_w1);
    cudaGetSymbolAddress(&pw2, g_w2);
    __half* hbuf = (__half*)ph;
    __half* ahi = (__half*)pah;
    __half *w1 = (__half*)pw1, *w2 = (__half*)pw2;

    cudaFuncSetAttribute(gemm_hmma, cudaFuncAttributeMaxDynamicSharedMemorySize, SMEM_TOTAL);

    deg_kernel<<<(NN + 255) / 256, 256>>>(ei);
    tohalf_kernel<<<(NN * D / 4 + 255) / 256, 256>>>(x, ahi, NN * D / 4);
    tohalf_kernel<<<(D * D / 4 + 255) / 256, 256>>>(Wt[0], w1, D * D / 4);
    tohalf_kernel<<<(D * D / 4 + 255) / 256, 256>>>(Wt[1], w2, D * D / 4);

    dim3 ggrid(D / 128, (NN + 127) / 128);  // (4, 782)
    gemm_hmma<<<ggrid, 256, SMEM_TOTAL>>>(ahi, w1, bt[0], hbuf);
    agg_half_kernel<<<NN, 128>>>(hbuf, ei, ahi);
    gemm_hmma<<<ggrid, 256, SMEM_TOTAL>>>(ahi, w2, bt[1], hbuf);
    agg_final_kernel<<<NN, 128>>>(hbuf, ei, out);
}